// round 7
// baseline (speedup 1.0000x reference)
#include <cuda_runtime.h>

#define NN 100000
#define NE 3200000
#define NG 64
#define NB 100               // scan blocks
#define NPB 1000             // nodes per scan block (NB*NPB == NN)

typedef unsigned long long ull;

// ---------------- scratch (device globals; no allocations allowed) ----------
__device__ float d_deg[NN];          // weighted degree -> dinv (in place)
__device__ int   d_cnt[NN];          // edge count per dst
__device__ int   d_ptr[NN + 1];      // CSR row offsets
__device__ int   d_fill[NN];         // scatter cursors
__device__ int   d_bsum[NB];         // per-block count totals
__device__ int   d_boff[NB];         // exclusive block offsets
__device__ int2  d_csr[NE];          // {src, __float_as_int(norm)}
__device__ float d_h1pre[NN * 64];   // x @ W1
__device__ float d_h2pre[NN * 32];   // relu(agg1+b1) @ W2  (fused epilogue)
__device__ float d_h2out[NN * 32];   // conv2 aggregated (pre bias/relu)
__device__ float d_pooled[NG * 32];

// ---------------- f32x2 helpers (Blackwell packed fp32) ---------------------
__device__ __forceinline__ ull pk2(float x) {
    ull r;
    asm("mov.b64 %0, {%1, %1};" : "=l"(r) : "f"(x));
    return r;
}
__device__ __forceinline__ void fma2(ull& d, ull a, ull b) {
    asm("fma.rn.f32x2 %0, %1, %2, %0;" : "+l"(d) : "l"(a), "l"(b));
}
__device__ __forceinline__ float2 up2(ull v) {
    float2 f;
    asm("mov.b64 {%0, %1}, %2;" : "=f"(f.x), "=f"(f.y) : "l"(v));
    return f;
}

// ---------------- init -------------------------------------------------------
__global__ void k_init() {
    int i = blockIdx.x * 256 + threadIdx.x;
    if (i < NN) { d_deg[i] = 1.0f; d_cnt[i] = 0; }   // self-loop weight 1
    if (i < NG * 32) d_pooled[i] = 0.0f;             // relu outputs >= 0
}

// ---------------- edge histogram (low-reg, high-occupancy) -------------------
__global__ void __launch_bounds__(256) k_hist(const int* __restrict__ ei,
                                              const float* __restrict__ ew) {
    int e = blockIdx.x * 256 + threadIdx.x;
    if (e >= NE) return;
    int d = ei[NE + e];
    atomicAdd(&d_deg[d], ew[e]);
    atomicAdd(&d_cnt[d], 1);
}

// ---------------- gemm1: d_h1pre[n,64] = x[n,256] @ W1[256,64] ---------------
__global__ void __launch_bounds__(256) k_gemm1(const float* __restrict__ x,
                                               const float* __restrict__ W1) {
    constexpr int K = 256, COLS = 64, CG = 16, KC = 64;   // ROWS = 128
    __shared__ __align__(16) float Ws[KC * COLS];

    int t = threadIdx.x;
    int ct = t % CG;
    int rt = t / CG;
    int row0 = blockIdx.x * 128 + rt * 8;

    const float* ap[8];
#pragma unroll
    for (int i = 0; i < 8; i++) {
        int r = row0 + i;
        if (r > NN - 1) r = NN - 1;
        ap[i] = x + (long long)r * K;
    }

    ull acc[8][2];
#pragma unroll
    for (int i = 0; i < 8; i++) { acc[i][0] = 0ULL; acc[i][1] = 0ULL; }

    for (int k0 = 0; k0 < K; k0 += KC) {
        __syncthreads();
        for (int i = t; i < KC * COLS / 4; i += 256)
            ((float4*)Ws)[i] = ((const float4*)(W1 + k0 * COLS))[i];
        __syncthreads();

#pragma unroll 2
        for (int kq = 0; kq < KC / 4; kq++) {
            float4 a[8];
#pragma unroll
            for (int i = 0; i < 8; i++) a[i] = *(const float4*)(ap[i] + k0 + kq * 4);
#pragma unroll
            for (int j = 0; j < 4; j++) {
                ulonglong2 w2 = *(const ulonglong2*)(Ws + (kq * 4 + j) * COLS + ct * 4);
#pragma unroll
                for (int i = 0; i < 8; i++) {
                    float av = (j == 0) ? a[i].x : (j == 1) ? a[i].y
                             : (j == 2) ? a[i].z : a[i].w;
                    ull aa = pk2(av);
                    fma2(acc[i][0], aa, w2.x);
                    fma2(acc[i][1], aa, w2.y);
                }
            }
        }
    }

#pragma unroll
    for (int i = 0; i < 8; i++) {
        int r = row0 + i;
        if (r < NN) {
            float2 p0 = up2(acc[i][0]);
            float2 p1 = up2(acc[i][1]);
            *(float4*)(d_h1pre + (long long)r * COLS + ct * 4) =
                make_float4(p0.x, p0.y, p1.x, p1.y);
        }
    }
}

// ---- hierarchical scan of d_cnt -> d_ptr (exclusive); rsqrt fused ----------
__global__ void __launch_bounds__(256) k_scanA() {    // per-block totals
    __shared__ int sm[8];
    int b = blockIdx.x, t = threadIdx.x;
    int s = 0;
    for (int i = t; i < NPB; i += 256) s += d_cnt[b * NPB + i];
#pragma unroll
    for (int o = 16; o; o >>= 1) s += __shfl_xor_sync(0xffffffffu, s, o);
    if ((t & 31) == 0) sm[t >> 5] = s;
    __syncthreads();
    if (t == 0) {
        int tot = 0;
#pragma unroll
        for (int i = 0; i < 8; i++) tot += sm[i];
        d_bsum[b] = tot;
    }
    // fused: deg -> rsqrt(deg)  (deg >= 1 always)
    for (int i = b * 256 + t; i < NN; i += NB * 256)
        d_deg[i] = rsqrtf(d_deg[i]);
}

__global__ void __launch_bounds__(128) k_scanB() {    // scan 100 partials
    __shared__ int sm[128];
    int t = threadIdx.x;
    sm[t] = (t < NB) ? d_bsum[t] : 0;
    __syncthreads();
#pragma unroll
    for (int off = 1; off < 128; off <<= 1) {
        int v = (t >= off) ? sm[t - off] : 0;
        __syncthreads();
        sm[t] += v;
        __syncthreads();
    }
    if (t < NB) d_boff[t] = sm[t] - d_bsum[t];   // exclusive
    if (t == 0) d_ptr[NN] = NE;
}

__global__ void __launch_bounds__(256) k_scanC() {    // in-block scan + write
    __shared__ int sm[256];
    int b = blockIdx.x, t = threadIdx.x;
    int base = b * NPB;
    int4 c = make_int4(0, 0, 0, 0);
    if (t < NPB / 4) c = ((const int4*)(d_cnt + base))[t];
    int tsum = c.x + c.y + c.z + c.w;
    sm[t] = tsum;
    __syncthreads();
#pragma unroll
    for (int off = 1; off < 256; off <<= 1) {
        int v = (t >= off) ? sm[t - off] : 0;
        __syncthreads();
        sm[t] += v;
        __syncthreads();
    }
    if (t < NPB / 4) {
        int run = d_boff[b] + sm[t] - tsum;
        int i = base + t * 4;
        d_ptr[i] = run;     d_fill[i] = run;     run += c.x;
        d_ptr[i + 1] = run; d_fill[i + 1] = run; run += c.y;
        d_ptr[i + 2] = run; d_fill[i + 2] = run; run += c.z;
        d_ptr[i + 3] = run; d_fill[i + 3] = run;
    }
}

__global__ void k_scatter(const int* __restrict__ ei, const float* __restrict__ ew) {
    int e = blockIdx.x * 256 + threadIdx.x;
    if (e >= NE) return;
    int s = ei[e];
    int d = ei[NE + e];
    float w = d_deg[s] * ew[e] * d_deg[d];
    int pos = atomicAdd(&d_fill[d], 1);
    d_csr[pos] = make_int2(s, __float_as_int(w));
}

// ------- agg1 (CSR gather, warp/node, MLP=4) + fused gemm2 epilogue ---------
// h2pre[n,32] = relu(agg1[n,64] + b1) @ W2[64,32]
__global__ void __launch_bounds__(256) k_agg1g2(const float* __restrict__ b1,
                                                const float* __restrict__ W2) {
    __shared__ __align__(16) float W2s[64 * 32];
    __shared__ float b1s[64];
    int t = threadIdx.x;
    for (int i = t; i < 64 * 32 / 4; i += 256)
        ((float4*)W2s)[i] = ((const float4*)W2)[i];
    if (t < 64) b1s[t] = b1[t];
    __syncthreads();

    int node = blockIdx.x * 8 + (t >> 5);
    if (node >= NN) return;
    int lane = t & 31;

    const ull* h1 = (const ull*)d_h1pre;   // float2 rows, 32 per node
    float dv = d_deg[node];
    ull acc;
    {
        ull v = h1[node * 32 + lane];
        acc = 0ULL;
        fma2(acc, pk2(dv * dv), v);        // self-loop
    }

    int beg = d_ptr[node], end = d_ptr[node + 1];
    int e = beg;
    for (; e + 4 <= end; e += 4) {         // uniform edge loads, MLP=4 gathers
        int2 q0 = d_csr[e];
        int2 q1 = d_csr[e + 1];
        int2 q2 = d_csr[e + 2];
        int2 q3 = d_csr[e + 3];
        ull v0 = h1[q0.x * 32 + lane];
        ull v1 = h1[q1.x * 32 + lane];
        ull v2 = h1[q2.x * 32 + lane];
        ull v3 = h1[q3.x * 32 + lane];
        fma2(acc, pk2(__int_as_float(q0.y)), v0);
        fma2(acc, pk2(__int_as_float(q1.y)), v1);
        fma2(acc, pk2(__int_as_float(q2.y)), v2);
        fma2(acc, pk2(__int_as_float(q3.y)), v3);
    }
    for (; e < end; e++) {
        int2 q = d_csr[e];
        ull v = h1[q.x * 32 + lane];
        fma2(acc, pk2(__int_as_float(q.y)), v);
    }

    // fused gemm2 epilogue: relu(acc + b1) @ W2 via warp broadcast
    float2 af = up2(acc);
    float a0 = fmaxf(af.x + b1s[2 * lane], 0.0f);
    float a1 = fmaxf(af.y + b1s[2 * lane + 1], 0.0f);
    float h2 = 0.0f;
#pragma unroll
    for (int j = 0; j < 32; j++) {
        float aj0 = __shfl_sync(0xffffffffu, a0, j);
        float aj1 = __shfl_sync(0xffffffffu, a1, j);
        h2 = fmaf(aj0, W2s[(2 * j) * 32 + lane], h2);
        h2 = fmaf(aj1, W2s[(2 * j + 1) * 32 + lane], h2);
    }
    d_h2pre[node * 32 + lane] = h2;
}

// ---------------- agg2: CSR gather, warp per node, MLP=4 ---------------------
__global__ void __launch_bounds__(256) k_agg2() {
    int node = blockIdx.x * 8 + (threadIdx.x >> 5);
    if (node >= NN) return;
    int lane = threadIdx.x & 31;

    float dv = d_deg[node];
    float acc = d_h2pre[node * 32 + lane] * dv * dv;

    int beg = d_ptr[node], end = d_ptr[node + 1];
    int e = beg;
    for (; e + 4 <= end; e += 4) {
        int2 q0 = d_csr[e];
        int2 q1 = d_csr[e + 1];
        int2 q2 = d_csr[e + 2];
        int2 q3 = d_csr[e + 3];
        float v0 = d_h2pre[q0.x * 32 + lane];
        float v1 = d_h2pre[q1.x * 32 + lane];
        float v2 = d_h2pre[q2.x * 32 + lane];
        float v3 = d_h2pre[q3.x * 32 + lane];
        acc = fmaf(__int_as_float(q0.y), v0, acc);
        acc = fmaf(__int_as_float(q1.y), v1, acc);
        acc = fmaf(__int_as_float(q2.y), v2, acc);
        acc = fmaf(__int_as_float(q3.y), v3, acc);
    }
    for (; e < end; e++) {
        int2 q = d_csr[e];
        acc = fmaf(__int_as_float(q.y), d_h2pre[q.x * 32 + lane], acc);
    }
    d_h2out[node * 32 + lane] = acc;
}

// ---------------- pooling: segment_max(relu(h2out + b2)), batch sorted ------
#define PN 16
__global__ void k_pool(const int* __restrict__ batch, const float* __restrict__ b2) {
    int tid = blockIdx.x * 256 + threadIdx.x;
    int c = tid & 31;
    int n0 = (tid >> 5) * PN;
    if (n0 >= NN) return;
    int nend = n0 + PN < NN ? n0 + PN : NN;
    float bb = b2[c];
    int g = batch[n0];
    float m = 0.0f;
    for (int n = n0; n < nend; n++) {
        int gn = batch[n];
        if (gn != g) {
            atomicMax((int*)&d_pooled[g * 32 + c], __float_as_int(m));
            g = gn; m = 0.0f;
        }
        float v = fmaxf(d_h2out[n * 32 + c] + bb, 0.0f);
        m = fmaxf(m, v);
    }
    atomicMax((int*)&d_pooled[g * 32 + c], __float_as_int(m));
}

// ---------------- final linear: out[64,4] = pooled @ Wlin + blin ------------
__global__ void k_final(const float* __restrict__ Wlin, const float* __restrict__ blin,
                        float* __restrict__ out) {
    int t = threadIdx.x;            // 256 = 64*4
    int g = t >> 2;
    int c = t & 3;
    float s = blin[c];
#pragma unroll
    for (int k = 0; k < 32; k++) s += d_pooled[g * 32 + k] * Wlin[k * 4 + c];
    out[g * 4 + c] = s;
}

// ---------------- launch -----------------------------------------------------
extern "C" void kernel_launch(void* const* d_in, const int* in_sizes, int n_in,
                              void* d_out, int out_size) {
    const float* x     = (const float*)d_in[0];
    const int*   ei    = (const int*)d_in[1];
    const float* ew    = (const float*)d_in[2];
    const int*   batch = (const int*)d_in[3];
    const float* W1    = (const float*)d_in[4];
    const float* b1    = (const float*)d_in[5];
    const float* W2    = (const float*)d_in[6];
    const float* b2    = (const float*)d_in[7];
    const float* Wlin  = (const float*)d_in[8];
    const float* blin  = (const float*)d_in[9];
    float* out = (float*)d_out;

    k_init<<<(NN + 255) / 256, 256>>>();
    k_hist<<<(NE + 255) / 256, 256>>>(ei, ew);
    k_gemm1<<<(NN + 127) / 128, 256>>>(x, W1);
    k_scanA<<<NB, 256>>>();                                    // + rsqrt
    k_scanB<<<1, 128>>>();
    k_scanC<<<NB, 256>>>();
    k_scatter<<<(NE + 255) / 256, 256>>>(ei, ew);

    k_agg1g2<<<(NN + 7) / 8, 256>>>(b1, W2);                   // agg1 + gemm2
    k_agg2<<<(NN + 7) / 8, 256>>>();

    k_pool<<<((NN / PN + 1) * 32 + 255) / 256, 256>>>(batch, b2);
    k_final<<<1, 256>>>(Wlin, blin, out);
}

// round 8
// speedup vs baseline: 1.0890x; 1.0890x over previous
#include <cuda_runtime.h>

#define NN 100000
#define NE 3200000
#define NG 64
#define NB 100               // scan blocks
#define NPB 1000             // nodes per scan block (NB*NPB == NN)

typedef unsigned long long ull;

// ---------------- scratch (device globals; no allocations allowed) ----------
__device__ float d_deg[NN];          // weighted degree -> dinv (in place)
__device__ int   d_cnt[NN];          // edge count per dst
__device__ int   d_ptr[NN + 1];      // CSR row offsets
__device__ int   d_fill[NN];         // scatter cursors
__device__ int   d_bsum[NB];         // per-block count totals
__device__ int   d_boff[NB];         // exclusive block offsets
__device__ int2  d_csr[NE];          // {src, __float_as_int(norm)}
__device__ float d_h1pre[NN * 64];   // x @ W1
__device__ float d_h1out[NN * 64];   // conv1 aggregated (pre bias/relu)
__device__ float d_h2pre[NN * 32];   // relu(h1out+b1) @ W2
__device__ float d_h2out[NN * 32];   // conv2 aggregated (pre bias/relu)
__device__ float d_pooled[NG * 32];

// ---------------- f32x2 helpers (Blackwell packed fp32) ---------------------
__device__ __forceinline__ ull pk2(float x) {
    ull r;
    asm("mov.b64 %0, {%1, %1};" : "=l"(r) : "f"(x));
    return r;
}
__device__ __forceinline__ void fma2(ull& d, ull a, ull b) {
    asm("fma.rn.f32x2 %0, %1, %2, %0;" : "+l"(d) : "l"(a), "l"(b));
}
__device__ __forceinline__ float2 up2(ull v) {
    float2 f;
    asm("mov.b64 {%0, %1}, %2;" : "=f"(f.x), "=f"(f.y) : "l"(v));
    return f;
}

// ---------------- init -------------------------------------------------------
__global__ void k_init() {
    int i = blockIdx.x * 256 + threadIdx.x;
    if (i < NN) { d_deg[i] = 1.0f; d_cnt[i] = 0; }   // self-loop weight 1
    if (i < NG * 32) d_pooled[i] = 0.0f;             // relu outputs >= 0
}

// ---------------- edge histogram ---------------------------------------------
__global__ void __launch_bounds__(256) k_hist(const int* __restrict__ ei,
                                              const float* __restrict__ ew) {
    int e = blockIdx.x * 256 + threadIdx.x;
    if (e >= NE) return;
    int d = ei[NE + e];
    atomicAdd(&d_deg[d], ew[e]);
    atomicAdd(&d_cnt[d], 1);
}

// ---- hierarchical scan of d_cnt -> d_ptr (exclusive); rsqrt fused ----------
__global__ void __launch_bounds__(256) k_scanA() {    // per-block totals
    __shared__ int sm[8];
    int b = blockIdx.x, t = threadIdx.x;
    int s = 0;
    for (int i = t; i < NPB; i += 256) s += d_cnt[b * NPB + i];
#pragma unroll
    for (int o = 16; o; o >>= 1) s += __shfl_xor_sync(0xffffffffu, s, o);
    if ((t & 31) == 0) sm[t >> 5] = s;
    __syncthreads();
    if (t == 0) {
        int tot = 0;
#pragma unroll
        for (int i = 0; i < 8; i++) tot += sm[i];
        d_bsum[b] = tot;
    }
    // fused: deg -> rsqrt(deg)  (deg >= 1 always)
    for (int i = b * 256 + t; i < NN; i += NB * 256)
        d_deg[i] = rsqrtf(d_deg[i]);
}

__global__ void __launch_bounds__(128) k_scanB() {    // scan 100 partials
    __shared__ int sm[128];
    int t = threadIdx.x;
    sm[t] = (t < NB) ? d_bsum[t] : 0;
    __syncthreads();
#pragma unroll
    for (int off = 1; off < 128; off <<= 1) {
        int v = (t >= off) ? sm[t - off] : 0;
        __syncthreads();
        sm[t] += v;
        __syncthreads();
    }
    if (t < NB) d_boff[t] = sm[t] - d_bsum[t];   // exclusive
    if (t == 0) d_ptr[NN] = NE;
}

__global__ void __launch_bounds__(256) k_scanC() {    // in-block scan + write
    __shared__ int sm[256];
    int b = blockIdx.x, t = threadIdx.x;
    int base = b * NPB;
    int4 c = make_int4(0, 0, 0, 0);
    if (t < NPB / 4) c = ((const int4*)(d_cnt + base))[t];
    int tsum = c.x + c.y + c.z + c.w;
    sm[t] = tsum;
    __syncthreads();
#pragma unroll
    for (int off = 1; off < 256; off <<= 1) {
        int v = (t >= off) ? sm[t - off] : 0;
        __syncthreads();
        sm[t] += v;
        __syncthreads();
    }
    if (t < NPB / 4) {
        int run = d_boff[b] + sm[t] - tsum;
        int i = base + t * 4;
        d_ptr[i] = run;     d_fill[i] = run;     run += c.x;
        d_ptr[i + 1] = run; d_fill[i + 1] = run; run += c.y;
        d_ptr[i + 2] = run; d_fill[i + 2] = run; run += c.z;
        d_ptr[i + 3] = run; d_fill[i + 3] = run;
    }
}

__global__ void k_scatter(const int* __restrict__ ei, const float* __restrict__ ew) {
    int e = blockIdx.x * 256 + threadIdx.x;
    if (e >= NE) return;
    int s = ei[e];
    int d = ei[NE + e];
    float w = d_deg[s] * ew[e] * d_deg[d];
    int pos = atomicAdd(&d_fill[d], 1);
    d_csr[pos] = make_int2(s, __float_as_int(w));
}

// ---------------- GEMM: C[n, COLS] = f(A[n, K]) @ W[K, COLS] ----------------
template <int K, int COLS, int MODE>
__global__ void __launch_bounds__(256) k_gemm(const float* __restrict__ Aarg,
                                              const float* __restrict__ W,
                                              const float* __restrict__ bias) {
    constexpr int CG = COLS / 4;
    constexpr int ROWS = (256 / CG) * 8;
    constexpr int KC = 64;
    __shared__ __align__(16) float Ws[KC * COLS];
    __shared__ __align__(16) float Bs[KC];
    const float* A = (MODE == 1) ? Aarg : d_h1out;
    float* C = (MODE == 1) ? d_h1pre : d_h2pre;

    int t = threadIdx.x;
    int ct = t % CG;
    int rt = t / CG;
    int row0 = blockIdx.x * ROWS + rt * 8;

    const float* ap[8];
#pragma unroll
    for (int i = 0; i < 8; i++) {
        int r = row0 + i;
        if (r > NN - 1) r = NN - 1;
        ap[i] = A + (long long)r * K;
    }

    ull acc[8][2];
#pragma unroll
    for (int i = 0; i < 8; i++) { acc[i][0] = 0ULL; acc[i][1] = 0ULL; }

    for (int k0 = 0; k0 < K; k0 += KC) {
        __syncthreads();
        for (int i = t; i < KC * COLS / 4; i += 256)
            ((float4*)Ws)[i] = ((const float4*)(W + k0 * COLS))[i];
        if (MODE == 2) {
            if (t < KC) Bs[t] = bias[k0 + t];
        }
        __syncthreads();

#pragma unroll 2
        for (int kq = 0; kq < KC / 4; kq++) {
            float4 a[8];
#pragma unroll
            for (int i = 0; i < 8; i++) a[i] = *(const float4*)(ap[i] + k0 + kq * 4);
            if (MODE == 2) {
                float4 b4 = *(const float4*)(Bs + kq * 4);
#pragma unroll
                for (int i = 0; i < 8; i++) {
                    a[i].x = fmaxf(a[i].x + b4.x, 0.0f);
                    a[i].y = fmaxf(a[i].y + b4.y, 0.0f);
                    a[i].z = fmaxf(a[i].z + b4.z, 0.0f);
                    a[i].w = fmaxf(a[i].w + b4.w, 0.0f);
                }
            }
#pragma unroll
            for (int j = 0; j < 4; j++) {
                ulonglong2 w2 = *(const ulonglong2*)(Ws + (kq * 4 + j) * COLS + ct * 4);
#pragma unroll
                for (int i = 0; i < 8; i++) {
                    float av = (j == 0) ? a[i].x : (j == 1) ? a[i].y
                             : (j == 2) ? a[i].z : a[i].w;
                    ull aa = pk2(av);
                    fma2(acc[i][0], aa, w2.x);
                    fma2(acc[i][1], aa, w2.y);
                }
            }
        }
    }

#pragma unroll
    for (int i = 0; i < 8; i++) {
        int r = row0 + i;
        if (r < NN) {
            float2 p0 = up2(acc[i][0]);
            float2 p1 = up2(acc[i][1]);
            *(float4*)(C + (long long)r * COLS + ct * 4) =
                make_float4(p0.x, p0.y, p1.x, p1.y);
        }
    }
}

// -------- agg1: CSR gather, warp/node, smem-staged edge records --------------
__global__ void __launch_bounds__(256) k_agg1() {
    __shared__ int2 es[8][32];
    int t = threadIdx.x;
    int wi = t >> 5;
    int lane = t & 31;
    int node = blockIdx.x * 8 + wi;
    if (node >= NN) return;

    const ull* h1 = (const ull*)d_h1pre;   // float2 rows, 32 per node
    float dv = d_deg[node];
    ull acc = 0ULL;
    fma2(acc, pk2(dv * dv), h1[node * 32 + lane]);   // self-loop

    int beg = d_ptr[node], end = d_ptr[node + 1];
    for (int base = beg; base < end; base += 32) {
        if (base + lane < end) es[wi][lane] = d_csr[base + lane];
        __syncwarp();
        int cnt = end - base; if (cnt > 32) cnt = 32;
        for (int j = 0; j < cnt; j++) {
            int2 q = es[wi][j];                       // broadcast LDS.64
            ull v = h1[q.x * 32 + lane];
            fma2(acc, pk2(__int_as_float(q.y)), v);
        }
        __syncwarp();
    }
    ((ull*)d_h1out)[node * 32 + lane] = acc;
}

// -------- agg2: CSR gather, warp/node, smem-staged ---------------------------
__global__ void __launch_bounds__(256) k_agg2() {
    __shared__ int2 es[8][32];
    int t = threadIdx.x;
    int wi = t >> 5;
    int lane = t & 31;
    int node = blockIdx.x * 8 + wi;
    if (node >= NN) return;

    float dv = d_deg[node];
    float acc = d_h2pre[node * 32 + lane] * dv * dv;

    int beg = d_ptr[node], end = d_ptr[node + 1];
    for (int base = beg; base < end; base += 32) {
        if (base + lane < end) es[wi][lane] = d_csr[base + lane];
        __syncwarp();
        int cnt = end - base; if (cnt > 32) cnt = 32;
        for (int j = 0; j < cnt; j++) {
            int2 q = es[wi][j];
            acc = fmaf(__int_as_float(q.y), d_h2pre[q.x * 32 + lane], acc);
        }
        __syncwarp();
    }
    d_h2out[node * 32 + lane] = acc;
}

// ---------------- pooling: segment_max(relu(h2out + b2)), batch sorted ------
#define PN 16
__global__ void k_pool(const int* __restrict__ batch, const float* __restrict__ b2) {
    int tid = blockIdx.x * 256 + threadIdx.x;
    int c = tid & 31;
    int n0 = (tid >> 5) * PN;
    if (n0 >= NN) return;
    int nend = n0 + PN < NN ? n0 + PN : NN;
    float bb = b2[c];
    int g = batch[n0];
    float m = 0.0f;
    for (int n = n0; n < nend; n++) {
        int gn = batch[n];
        if (gn != g) {
            atomicMax((int*)&d_pooled[g * 32 + c], __float_as_int(m));
            g = gn; m = 0.0f;
        }
        float v = fmaxf(d_h2out[n * 32 + c] + bb, 0.0f);
        m = fmaxf(m, v);
    }
    atomicMax((int*)&d_pooled[g * 32 + c], __float_as_int(m));
}

// ---------------- final linear: out[64,4] = pooled @ Wlin + blin ------------
__global__ void k_final(const float* __restrict__ Wlin, const float* __restrict__ blin,
                        float* __restrict__ out) {
    int t = threadIdx.x;            // 256 = 64*4
    int g = t >> 2;
    int c = t & 3;
    float s = blin[c];
#pragma unroll
    for (int k = 0; k < 32; k++) s += d_pooled[g * 32 + k] * Wlin[k * 4 + c];
    out[g * 4 + c] = s;
}

// ---------------- launch -----------------------------------------------------
extern "C" void kernel_launch(void* const* d_in, const int* in_sizes, int n_in,
                              void* d_out, int out_size) {
    const float* x     = (const float*)d_in[0];
    const int*   ei    = (const int*)d_in[1];
    const float* ew    = (const float*)d_in[2];
    const int*   batch = (const int*)d_in[3];
    const float* W1    = (const float*)d_in[4];
    const float* b1    = (const float*)d_in[5];
    const float* W2    = (const float*)d_in[6];
    const float* b2    = (const float*)d_in[7];
    const float* Wlin  = (const float*)d_in[8];
    const float* blin  = (const float*)d_in[9];
    float* out = (float*)d_out;

    k_init<<<(NN + 255) / 256, 256>>>();
    k_hist<<<(NE + 255) / 256, 256>>>(ei, ew);
    k_scanA<<<NB, 256>>>();                                    // + rsqrt
    k_scanB<<<1, 128>>>();
    k_scanC<<<NB, 256>>>();
    k_scatter<<<(NE + 255) / 256, 256>>>(ei, ew);

    k_gemm<256, 64, 1><<<(NN + 127) / 128, 256>>>(x, W1, nullptr);
    k_agg1<<<(NN + 7) / 8, 256>>>();

    k_gemm<64, 32, 2><<<(NN + 255) / 256, 256>>>(nullptr, W2, b1);
    k_agg2<<<(NN + 7) / 8, 256>>>();

    k_pool<<<((NN / PN + 1) * 32 + 255) / 256, 256>>>(batch, b2);
    k_final<<<1, 256>>>(Wlin, blin, out);
}

// round 9
// speedup vs baseline: 1.2019x; 1.1038x over previous
#include <cuda_runtime.h>

#define NN 100000
#define NE 3200000
#define NG 64
#define NB 100               // scan blocks
#define NPB 1000             // nodes per scan block (NB*NPB == NN)

typedef unsigned long long ull;

// ---------------- scratch (device globals; no allocations allowed) ----------
__device__ float d_deg[NN];          // weighted degree -> dinv (in place)
__device__ int   d_cnt[NN];          // edge count per dst
__device__ int   d_ptr[NN + 1];      // CSR row offsets
__device__ int   d_fill[NN];         // scatter cursors
__device__ int   d_bsum[NB];         // per-block count totals
__device__ int   d_boff[NB];         // exclusive block offsets
__device__ int2  d_csr[NE];          // {src, __float_as_int(norm)}
__device__ float d_h1pre[NN * 64];   // x @ W1
__device__ float d_h1out[NN * 64];   // conv1 aggregated (pre bias/relu)
__device__ float d_h2pre[NN * 32];   // relu(h1out+b1) @ W2
__device__ float d_h2out[NN * 32];   // conv2 aggregated (pre bias/relu)
__device__ float d_pooled[NG * 32];

// --------- side stream + events for captured fork/join (created pre-main) ---
static cudaStream_t g_s2;
static cudaEvent_t  g_evF, g_evJ;
static struct StreamInit {
    StreamInit() {
        cudaStreamCreateWithFlags(&g_s2, cudaStreamNonBlocking);
        cudaEventCreateWithFlags(&g_evF, cudaEventDisableTiming);
        cudaEventCreateWithFlags(&g_evJ, cudaEventDisableTiming);
    }
} g_streamInit;

// ---------------- f32x2 helpers (Blackwell packed fp32) ---------------------
__device__ __forceinline__ ull pk2(float x) {
    ull r;
    asm("mov.b64 %0, {%1, %1};" : "=l"(r) : "f"(x));
    return r;
}
__device__ __forceinline__ void fma2(ull& d, ull a, ull b) {
    asm("fma.rn.f32x2 %0, %1, %2, %0;" : "+l"(d) : "l"(a), "l"(b));
}
__device__ __forceinline__ float2 up2(ull v) {
    float2 f;
    asm("mov.b64 {%0, %1}, %2;" : "=f"(f.x), "=f"(f.y) : "l"(v));
    return f;
}

// ---------------- init -------------------------------------------------------
__global__ void k_init() {
    int i = blockIdx.x * 256 + threadIdx.x;
    if (i < NN) { d_deg[i] = 1.0f; d_cnt[i] = 0; }   // self-loop weight 1
    if (i < NG * 32) d_pooled[i] = 0.0f;             // relu outputs >= 0
}

// ---------------- edge histogram ---------------------------------------------
__global__ void __launch_bounds__(256) k_hist(const int* __restrict__ ei,
                                              const float* __restrict__ ew) {
    int e = blockIdx.x * 256 + threadIdx.x;
    if (e >= NE) return;
    int d = ei[NE + e];
    atomicAdd(&d_deg[d], ew[e]);
    atomicAdd(&d_cnt[d], 1);
}

// ---- hierarchical scan of d_cnt -> d_ptr (exclusive); rsqrt fused ----------
__global__ void __launch_bounds__(256) k_scanA() {    // per-block totals
    __shared__ int sm[8];
    int b = blockIdx.x, t = threadIdx.x;
    int s = 0;
    for (int i = t; i < NPB; i += 256) s += d_cnt[b * NPB + i];
#pragma unroll
    for (int o = 16; o; o >>= 1) s += __shfl_xor_sync(0xffffffffu, s, o);
    if ((t & 31) == 0) sm[t >> 5] = s;
    __syncthreads();
    if (t == 0) {
        int tot = 0;
#pragma unroll
        for (int i = 0; i < 8; i++) tot += sm[i];
        d_bsum[b] = tot;
    }
    // fused: deg -> rsqrt(deg)  (deg >= 1 always)
    for (int i = b * 256 + t; i < NN; i += NB * 256)
        d_deg[i] = rsqrtf(d_deg[i]);
}

__global__ void __launch_bounds__(128) k_scanB() {    // scan 100 partials
    __shared__ int sm[128];
    int t = threadIdx.x;
    sm[t] = (t < NB) ? d_bsum[t] : 0;
    __syncthreads();
#pragma unroll
    for (int off = 1; off < 128; off <<= 1) {
        int v = (t >= off) ? sm[t - off] : 0;
        __syncthreads();
        sm[t] += v;
        __syncthreads();
    }
    if (t < NB) d_boff[t] = sm[t] - d_bsum[t];   // exclusive
    if (t == 0) d_ptr[NN] = NE;
}

__global__ void __launch_bounds__(256) k_scanC() {    // in-block scan + write
    __shared__ int sm[256];
    int b = blockIdx.x, t = threadIdx.x;
    int base = b * NPB;
    int4 c = make_int4(0, 0, 0, 0);
    if (t < NPB / 4) c = ((const int4*)(d_cnt + base))[t];
    int tsum = c.x + c.y + c.z + c.w;
    sm[t] = tsum;
    __syncthreads();
#pragma unroll
    for (int off = 1; off < 256; off <<= 1) {
        int v = (t >= off) ? sm[t - off] : 0;
        __syncthreads();
        sm[t] += v;
        __syncthreads();
    }
    if (t < NPB / 4) {
        int run = d_boff[b] + sm[t] - tsum;
        int i = base + t * 4;
        d_ptr[i] = run;     d_fill[i] = run;     run += c.x;
        d_ptr[i + 1] = run; d_fill[i + 1] = run; run += c.y;
        d_ptr[i + 2] = run; d_fill[i + 2] = run; run += c.z;
        d_ptr[i + 3] = run; d_fill[i + 3] = run;
    }
}

__global__ void k_scatter(const int* __restrict__ ei, const float* __restrict__ ew) {
    int e = blockIdx.x * 256 + threadIdx.x;
    if (e >= NE) return;
    int s = ei[e];
    int d = ei[NE + e];
    float w = d_deg[s] * ew[e] * d_deg[d];
    int pos = atomicAdd(&d_fill[d], 1);
    d_csr[pos] = make_int2(s, __float_as_int(w));
}

// ---------------- GEMM: C[n, COLS] = f(A[n, K]) @ W[K, COLS] ----------------
template <int K, int COLS, int MODE>
__global__ void __launch_bounds__(256) k_gemm(const float* __restrict__ Aarg,
                                              const float* __restrict__ W,
                                              const float* __restrict__ bias) {
    constexpr int CG = COLS / 4;
    constexpr int ROWS = (256 / CG) * 8;
    constexpr int KC = 64;
    __shared__ __align__(16) float Ws[KC * COLS];
    __shared__ __align__(16) float Bs[KC];
    const float* A = (MODE == 1) ? Aarg : d_h1out;
    float* C = (MODE == 1) ? d_h1pre : d_h2pre;

    int t = threadIdx.x;
    int ct = t % CG;
    int rt = t / CG;
    int row0 = blockIdx.x * ROWS + rt * 8;

    const float* ap[8];
#pragma unroll
    for (int i = 0; i < 8; i++) {
        int r = row0 + i;
        if (r > NN - 1) r = NN - 1;
        ap[i] = A + (long long)r * K;
    }

    ull acc[8][2];
#pragma unroll
    for (int i = 0; i < 8; i++) { acc[i][0] = 0ULL; acc[i][1] = 0ULL; }

    for (int k0 = 0; k0 < K; k0 += KC) {
        __syncthreads();
        for (int i = t; i < KC * COLS / 4; i += 256)
            ((float4*)Ws)[i] = ((const float4*)(W + k0 * COLS))[i];
        if (MODE == 2) {
            if (t < KC) Bs[t] = bias[k0 + t];
        }
        __syncthreads();

#pragma unroll 2
        for (int kq = 0; kq < KC / 4; kq++) {
            float4 a[8];
#pragma unroll
            for (int i = 0; i < 8; i++) a[i] = *(const float4*)(ap[i] + k0 + kq * 4);
            if (MODE == 2) {
                float4 b4 = *(const float4*)(Bs + kq * 4);
#pragma unroll
                for (int i = 0; i < 8; i++) {
                    a[i].x = fmaxf(a[i].x + b4.x, 0.0f);
                    a[i].y = fmaxf(a[i].y + b4.y, 0.0f);
                    a[i].z = fmaxf(a[i].z + b4.z, 0.0f);
                    a[i].w = fmaxf(a[i].w + b4.w, 0.0f);
                }
            }
#pragma unroll
            for (int j = 0; j < 4; j++) {
                ulonglong2 w2 = *(const ulonglong2*)(Ws + (kq * 4 + j) * COLS + ct * 4);
#pragma unroll
                for (int i = 0; i < 8; i++) {
                    float av = (j == 0) ? a[i].x : (j == 1) ? a[i].y
                             : (j == 2) ? a[i].z : a[i].w;
                    ull aa = pk2(av);
                    fma2(acc[i][0], aa, w2.x);
                    fma2(acc[i][1], aa, w2.y);
                }
            }
        }
    }

#pragma unroll
    for (int i = 0; i < 8; i++) {
        int r = row0 + i;
        if (r < NN) {
            float2 p0 = up2(acc[i][0]);
            float2 p1 = up2(acc[i][1]);
            *(float4*)(C + (long long)r * COLS + ct * 4) =
                make_float4(p0.x, p0.y, p1.x, p1.y);
        }
    }
}

// -------- agg1: CSR gather, warp/node, smem-staged edge records --------------
__global__ void __launch_bounds__(256) k_agg1() {
    __shared__ int2 es[8][32];
    int t = threadIdx.x;
    int wi = t >> 5;
    int lane = t & 31;
    int node = blockIdx.x * 8 + wi;
    if (node >= NN) return;

    const ull* h1 = (const ull*)d_h1pre;   // float2 rows, 32 per node
    float dv = d_deg[node];
    ull acc = 0ULL;
    fma2(acc, pk2(dv * dv), h1[node * 32 + lane]);   // self-loop

    int beg = d_ptr[node], end = d_ptr[node + 1];
    for (int base = beg; base < end; base += 32) {
        if (base + lane < end) es[wi][lane] = d_csr[base + lane];
        __syncwarp();
        int cnt = end - base; if (cnt > 32) cnt = 32;
        for (int j = 0; j < cnt; j++) {
            int2 q = es[wi][j];                       // broadcast LDS.64
            ull v = h1[q.x * 32 + lane];
            fma2(acc, pk2(__int_as_float(q.y)), v);
        }
        __syncwarp();
    }
    ((ull*)d_h1out)[node * 32 + lane] = acc;
}

// -------- agg2: CSR gather, warp/node, smem-staged ---------------------------
__global__ void __launch_bounds__(256) k_agg2() {
    __shared__ int2 es[8][32];
    int t = threadIdx.x;
    int wi = t >> 5;
    int lane = t & 31;
    int node = blockIdx.x * 8 + wi;
    if (node >= NN) return;

    float dv = d_deg[node];
    float acc = d_h2pre[node * 32 + lane] * dv * dv;

    int beg = d_ptr[node], end = d_ptr[node + 1];
    for (int base = beg; base < end; base += 32) {
        if (base + lane < end) es[wi][lane] = d_csr[base + lane];
        __syncwarp();
        int cnt = end - base; if (cnt > 32) cnt = 32;
        for (int j = 0; j < cnt; j++) {
            int2 q = es[wi][j];
            acc = fmaf(__int_as_float(q.y), d_h2pre[q.x * 32 + lane], acc);
        }
        __syncwarp();
    }
    d_h2out[node * 32 + lane] = acc;
}

// ---------------- pooling: segment_max(relu(h2out + b2)), batch sorted ------
#define PN 16
__global__ void k_pool(const int* __restrict__ batch, const float* __restrict__ b2) {
    int tid = blockIdx.x * 256 + threadIdx.x;
    int c = tid & 31;
    int n0 = (tid >> 5) * PN;
    if (n0 >= NN) return;
    int nend = n0 + PN < NN ? n0 + PN : NN;
    float bb = b2[c];
    int g = batch[n0];
    float m = 0.0f;
    for (int n = n0; n < nend; n++) {
        int gn = batch[n];
        if (gn != g) {
            atomicMax((int*)&d_pooled[g * 32 + c], __float_as_int(m));
            g = gn; m = 0.0f;
        }
        float v = fmaxf(d_h2out[n * 32 + c] + bb, 0.0f);
        m = fmaxf(m, v);
    }
    atomicMax((int*)&d_pooled[g * 32 + c], __float_as_int(m));
}

// ---------------- final linear: out[64,4] = pooled @ Wlin + blin ------------
__global__ void k_final(const float* __restrict__ Wlin, const float* __restrict__ blin,
                        float* __restrict__ out) {
    int t = threadIdx.x;            // 256 = 64*4
    int g = t >> 2;
    int c = t & 3;
    float s = blin[c];
#pragma unroll
    for (int k = 0; k < 32; k++) s += d_pooled[g * 32 + k] * Wlin[k * 4 + c];
    out[g * 4 + c] = s;
}

// ---------------- launch -----------------------------------------------------
extern "C" void kernel_launch(void* const* d_in, const int* in_sizes, int n_in,
                              void* d_out, int out_size) {
    const float* x     = (const float*)d_in[0];
    const int*   ei    = (const int*)d_in[1];
    const float* ew    = (const float*)d_in[2];
    const int*   batch = (const int*)d_in[3];
    const float* W1    = (const float*)d_in[4];
    const float* b1    = (const float*)d_in[5];
    const float* W2    = (const float*)d_in[6];
    const float* b2    = (const float*)d_in[7];
    const float* Wlin  = (const float*)d_in[8];
    const float* blin  = (const float*)d_in[9];
    float* out = (float*)d_out;

    // fork: gemm1 (FMA-bound) runs on g_s2 while CSR build (atomic/LSU-bound)
    // runs on the main stream. Join before k_agg1 which needs both.
    cudaEventRecord(g_evF, 0);
    cudaStreamWaitEvent(g_s2, g_evF, 0);
    k_gemm<256, 64, 1><<<(NN + 127) / 128, 256, 0, g_s2>>>(x, W1, nullptr);
    cudaEventRecord(g_evJ, g_s2);

    k_init<<<(NN + 255) / 256, 256>>>();
    k_hist<<<(NE + 255) / 256, 256>>>(ei, ew);
    k_scanA<<<NB, 256>>>();                                    // + rsqrt
    k_scanB<<<1, 128>>>();
    k_scanC<<<NB, 256>>>();
    k_scatter<<<(NE + 255) / 256, 256>>>(ei, ew);

    cudaStreamWaitEvent(0, g_evJ, 0);                          // join
    k_agg1<<<(NN + 7) / 8, 256>>>();

    k_gemm<64, 32, 2><<<(NN + 255) / 256, 256>>>(nullptr, W2, b1);
    k_agg2<<<(NN + 7) / 8, 256>>>();

    k_pool<<<((NN / PN + 1) * 32 + 255) / 256, 256>>>(batch, b2);
    k_final<<<1, 256>>>(Wlin, blin, out);
}